// round 3
// baseline (speedup 1.0000x reference)
#include <cuda_runtime.h>
#include <math.h>

#define N_NODES 50000
#define N_EDGESC 400000
#define H 128
#define NT 2
#define FEAT 4

// ---------------- device scratch (no runtime allocation allowed) ----------------
__device__ float g_h[N_NODES * H];          // 25.6 MB
__device__ float g_agg[N_NODES * H];        // 25.6 MB
__device__ float g_gi[N_NODES * 3 * H];     // 76.8 MB
__device__ float g_gh[N_NODES * 3 * H];     // 76.8 MB
__device__ int   g_perm[N_EDGESC];          // 1.6 MB
__device__ int   g_cnt[2];
__device__ int   g_cursor[2];

__device__ __forceinline__ float sigm(float v) { return 1.0f / (1.0f + expf(-v)); }

// ---------------- edge partition by type ----------------
__global__ void k_zero_cnt() {
    if (threadIdx.x < 2) g_cnt[threadIdx.x] = 0;
}

__global__ void k_count(const int* __restrict__ et) {
    __shared__ int lc[2];
    if (threadIdx.x < 2) lc[threadIdx.x] = 0;
    __syncthreads();
    int e = blockIdx.x * blockDim.x + threadIdx.x;
    if (e < N_EDGESC) atomicAdd(&lc[et[e]], 1);
    __syncthreads();
    if (threadIdx.x < 2) atomicAdd(&g_cnt[threadIdx.x], lc[threadIdx.x]);
}

__global__ void k_seed() {
    g_cursor[0] = 0;
    g_cursor[1] = g_cnt[0];
}

__global__ void k_scatter(const int* __restrict__ et) {
    __shared__ int lc[2];
    __shared__ int base[2];
    if (threadIdx.x < 2) lc[threadIdx.x] = 0;
    __syncthreads();
    int e = blockIdx.x * blockDim.x + threadIdx.x;
    int t = 0, rank = 0;
    bool valid = (e < N_EDGESC);
    if (valid) {
        t = et[e];
        rank = atomicAdd(&lc[t], 1);
    }
    __syncthreads();
    if (threadIdx.x < 2) base[threadIdx.x] = atomicAdd(&g_cursor[threadIdx.x], lc[threadIdx.x]);
    __syncthreads();
    if (valid) g_perm[base[t] + rank] = e;
}

// ---------------- h = relu(x @ W_in + b_in) ----------------
__global__ void k_init(const float* __restrict__ x, const float* __restrict__ Win,
                       const float* __restrict__ bin) {
    __shared__ float sW[FEAT * H];
    __shared__ float sb[H];
    for (int i = threadIdx.x; i < FEAT * H; i += blockDim.x) sW[i] = Win[i];
    if (threadIdx.x < H) sb[threadIdx.x] = bin[threadIdx.x];
    __syncthreads();
    int idx = blockIdx.x * blockDim.x + threadIdx.x;
    if (idx >= N_NODES * H) return;
    int n = idx >> 7, c = idx & 127;
    float4 xr = ((const float4*)x)[n];
    float v = sb[c] + xr.x * sW[c] + xr.y * sW[H + c] + xr.z * sW[2 * H + c] + xr.w * sW[3 * H + c];
    g_h[idx] = fmaxf(v, 0.0f);
}

__global__ void k_zero_agg() {
    int i = blockIdx.x * blockDim.x + threadIdx.x;
    if (i < N_NODES * H) g_agg[i] = 0.0f;
}

// ---------------- edge MLP + scatter-add ----------------
// One block = 64 edges (one type), 256 threads, 4x8 register tile.
// smem: sA 64x256 (reused as sC 64x128), sW 32x128, sSrc/sDst 64 each.
__global__ __launch_bounds__(256, 2)
void k_edge_mlp(const int* __restrict__ edge_index,
                const float* __restrict__ W1, const float* __restrict__ b1,
                const float* __restrict__ W2, const float* __restrict__ b2, int l) {
    extern __shared__ float smem[];
    float* sA = smem;                  // 64*256
    float* sW = smem + 64 * 256;       // 32*128
    int* sSrc = (int*)(sW + 32 * 128); // 64
    int* sDst = sSrc + 64;             // 64

    int cnt0 = g_cnt[0];
    int nb0 = (cnt0 + 63) >> 6;
    int type, start, cnt, permBase;
    if ((int)blockIdx.x < nb0) {
        type = 0; start = blockIdx.x * 64; cnt = cnt0; permBase = 0;
    } else {
        type = 1; start = ((int)blockIdx.x - nb0) * 64;
        cnt = N_EDGESC - cnt0; permBase = cnt0;
        if (start >= cnt) return;
    }

    if (threadIdx.x < 64) {
        int g = start + threadIdx.x;
        int s = -1, d = -1;
        if (g < cnt) {
            int e = g_perm[permBase + g];
            s = edge_index[e];
            d = edge_index[N_EDGESC + e];
        }
        sSrc[threadIdx.x] = s;
        sDst[threadIdx.x] = d;
    }
    __syncthreads();

    // gather cat = [h[src], h[dst]] rows
    for (int t = threadIdx.x; t < 64 * 64; t += 256) {  // float4 granularity
        int r = t >> 6;
        int c4 = t & 63;
        int node = (c4 < 32) ? sSrc[r] : sDst[r];
        int cc = (c4 < 32) ? c4 : (c4 - 32);
        float4 v = make_float4(0.f, 0.f, 0.f, 0.f);
        if (node >= 0) v = ((const float4*)(g_h + (size_t)node * H))[cc];
        ((float4*)sA)[t] = v;
    }

    const float* W1t = W1 + (size_t)(l * NT + type) * (2 * H * H);
    const float* b1t = b1 + (l * NT + type) * H;
    const float* W2t = W2 + (size_t)(l * NT + type) * (H * H);
    const float* b2t = b2 + (l * NT + type) * H;

    int ty = threadIdx.x >> 4, tx = threadIdx.x & 15;
    const float4* sW4 = (const float4*)sW;

    float acc[4][8];
#pragma unroll
    for (int i = 0; i < 4; ++i)
#pragma unroll
        for (int j = 0; j < 8; ++j) acc[i][j] = 0.f;

    // GEMM1: [64x256] @ [256x128]
    for (int kc = 0; kc < 8; ++kc) {
        __syncthreads();
        for (int t = threadIdx.x; t < 32 * 32; t += 256) {
            int wr = t >> 5;
            ((float4*)sW)[t] = *(const float4*)(W1t + (kc * 32 + wr) * H + (t & 31) * 4);
        }
        __syncthreads();
#pragma unroll
        for (int k = 0; k < 32; ++k) {
            float4 bA = sW4[k * 32 + tx];
            float4 bB = sW4[k * 32 + 16 + tx];
            float bv[8] = {bA.x, bA.y, bA.z, bA.w, bB.x, bB.y, bB.z, bB.w};
            float av[4];
#pragma unroll
            for (int i = 0; i < 4; ++i) av[i] = sA[(ty + 16 * i) * 256 + kc * 32 + k];
#pragma unroll
            for (int i = 0; i < 4; ++i)
#pragma unroll
                for (int j = 0; j < 8; ++j) acc[i][j] += av[i] * bv[j];
        }
    }

    // hidden = relu(acc + b1), write to sC (reuse sA)
    float bb[8];
#pragma unroll
    for (int j = 0; j < 8; ++j) bb[j] = b1t[tx * 4 + (j >> 2) * 64 + (j & 3)];
    __syncthreads();  // everyone done reading sA
    float* sC = sA;
#pragma unroll
    for (int i = 0; i < 4; ++i) {
#pragma unroll
        for (int jj = 0; jj < 2; ++jj) {
            float4 v;
            v.x = fmaxf(acc[i][jj * 4 + 0] + bb[jj * 4 + 0], 0.f);
            v.y = fmaxf(acc[i][jj * 4 + 1] + bb[jj * 4 + 1], 0.f);
            v.z = fmaxf(acc[i][jj * 4 + 2] + bb[jj * 4 + 2], 0.f);
            v.w = fmaxf(acc[i][jj * 4 + 3] + bb[jj * 4 + 3], 0.f);
            ((float4*)sC)[((ty + 16 * i) * 128 + tx * 4 + jj * 64) >> 2] = v;
        }
    }

    // GEMM2: [64x128] @ [128x128]
    float acc2[4][8];
#pragma unroll
    for (int i = 0; i < 4; ++i)
#pragma unroll
        for (int j = 0; j < 8; ++j) acc2[i][j] = 0.f;

    for (int kc = 0; kc < 4; ++kc) {
        __syncthreads();
        for (int t = threadIdx.x; t < 32 * 32; t += 256) {
            int wr = t >> 5;
            ((float4*)sW)[t] = *(const float4*)(W2t + (kc * 32 + wr) * H + (t & 31) * 4);
        }
        __syncthreads();
#pragma unroll
        for (int k = 0; k < 32; ++k) {
            float4 bA = sW4[k * 32 + tx];
            float4 bB = sW4[k * 32 + 16 + tx];
            float bv[8] = {bA.x, bA.y, bA.z, bA.w, bB.x, bB.y, bB.z, bB.w};
            float av[4];
#pragma unroll
            for (int i = 0; i < 4; ++i) av[i] = sC[(ty + 16 * i) * 128 + kc * 32 + k];
#pragma unroll
            for (int i = 0; i < 4; ++i)
#pragma unroll
                for (int j = 0; j < 8; ++j) acc2[i][j] += av[i] * bv[j];
        }
    }

    // epilogue: msgs = acc2 + b2, scatter-add into agg[dst]
#pragma unroll
    for (int j = 0; j < 8; ++j) bb[j] = b2t[tx * 4 + (j >> 2) * 64 + (j & 3)];
#pragma unroll
    for (int i = 0; i < 4; ++i) {
        int d = sDst[ty + 16 * i];
        if (d < 0) continue;
        float* aggp = g_agg + (size_t)d * H;
#pragma unroll
        for (int j = 0; j < 8; ++j) {
            int col = tx * 4 + (j >> 2) * 64 + (j & 3);
            atomicAdd(aggp + col, acc2[i][j] + bb[j]);
        }
    }
}

// ---------------- GRU GEMMs: gi = agg@W_ih+b_ih (z=0), gh = h@W_hh+b_hh (z=1) ----------------
__global__ __launch_bounds__(256)
void k_gru_gemm(const float* __restrict__ Wih, const float* __restrict__ bih,
                const float* __restrict__ Whh, const float* __restrict__ bhh, int l) {
    extern __shared__ float smem[];
    float* sA = smem;            // 64*128
    float* sW = smem + 64 * H;   // 32*128

    const float* A; const float* W; const float* b; float* C;
    if (blockIdx.z == 0) { A = g_agg; W = Wih + (size_t)l * H * 3 * H; b = bih + l * 3 * H; C = g_gi; }
    else                 { A = g_h;   W = Whh + (size_t)l * H * 3 * H; b = bhh + l * 3 * H; C = g_gh; }

    int m0 = blockIdx.x * 64;
    int c0 = blockIdx.y * 128;

    for (int t = threadIdx.x; t < 64 * 32; t += 256) {  // float4 units
        int r = t >> 5;
        int c4 = t & 31;
        int m = m0 + r;
        float4 v = make_float4(0.f, 0.f, 0.f, 0.f);
        if (m < N_NODES) v = ((const float4*)(A + (size_t)m * H))[c4];
        ((float4*)sA)[t] = v;
    }

    int ty = threadIdx.x >> 4, tx = threadIdx.x & 15;
    const float4* sW4 = (const float4*)sW;
    float acc[4][8];
#pragma unroll
    for (int i = 0; i < 4; ++i)
#pragma unroll
        for (int j = 0; j < 8; ++j) acc[i][j] = 0.f;

    for (int kc = 0; kc < 4; ++kc) {
        __syncthreads();
        for (int t = threadIdx.x; t < 32 * 32; t += 256) {
            int wr = t >> 5;
            ((float4*)sW)[t] = *(const float4*)(W + (kc * 32 + wr) * (3 * H) + c0 + (t & 31) * 4);
        }
        __syncthreads();
#pragma unroll
        for (int k = 0; k < 32; ++k) {
            float4 bA = sW4[k * 32 + tx];
            float4 bB = sW4[k * 32 + 16 + tx];
            float bv[8] = {bA.x, bA.y, bA.z, bA.w, bB.x, bB.y, bB.z, bB.w};
            float av[4];
#pragma unroll
            for (int i = 0; i < 4; ++i) av[i] = sA[(ty + 16 * i) * H + kc * 32 + k];
#pragma unroll
            for (int i = 0; i < 4; ++i)
#pragma unroll
                for (int j = 0; j < 8; ++j) acc[i][j] += av[i] * bv[j];
        }
    }

#pragma unroll
    for (int i = 0; i < 4; ++i) {
        int m = m0 + ty + 16 * i;
        if (m >= N_NODES) continue;
#pragma unroll
        for (int j = 0; j < 8; ++j) {
            int col = tx * 4 + (j >> 2) * 64 + (j & 3);
            C[(size_t)m * 384 + c0 + col] = acc[i][j] + b[c0 + col];
        }
    }
}

__global__ void k_gru_combine() {
    int idx = blockIdx.x * blockDim.x + threadIdx.x;
    if (idx >= N_NODES * H) return;
    int n = idx >> 7, c = idx & 127;
    const float* gi = g_gi + (size_t)n * 384;
    const float* gh = g_gh + (size_t)n * 384;
    float r = sigm(gi[c] + gh[c]);
    float z = sigm(gi[128 + c] + gh[128 + c]);
    float nn = tanhf(gi[256 + c] + r * gh[256 + c]);
    g_h[idx] = (1.0f - z) * nn + z * g_h[idx];
}

// ---------------- readout: out = relu(h[:nd] @ Wr1 + br1) @ Wr2 + br2 ----------------
__global__ __launch_bounds__(256)
void k_readout(const float* __restrict__ Wr1, const float* __restrict__ br1,
               const float* __restrict__ Wr2, const float* __restrict__ br2,
               float* __restrict__ out, int nd) {
    extern __shared__ float smem[];
    float* sW1 = smem;              // 128*128
    float* sb1 = sW1 + H * H;       // 128
    float* sW2 = sb1 + H;           // 128
    float* sHrow = sW2 + H;         // 8 * 128

    for (int t = threadIdx.x; t < (H * H) / 4; t += blockDim.x)
        ((float4*)sW1)[t] = ((const float4*)Wr1)[t];
    if (threadIdx.x < H) {
        sb1[threadIdx.x] = br1[threadIdx.x];
        sW2[threadIdx.x] = Wr2[threadIdx.x];
    }
    __syncthreads();

    int w = threadIdx.x >> 5, lane = threadIdx.x & 31;
    float* myrow = sHrow + w * H;
    float b2v = br2[0];

    for (int n = blockIdx.x * 8 + w; n < nd; n += gridDim.x * 8) {
        ((float4*)myrow)[lane] = ((const float4*)(g_h + (size_t)n * H))[lane];
        __syncwarp();
        float hid0 = 0.f, hid1 = 0.f, hid2 = 0.f, hid3 = 0.f;
#pragma unroll 4
        for (int k = 0; k < H; ++k) {
            float a = myrow[k];
            float4 wv = ((const float4*)sW1)[k * 32 + lane];
            hid0 += a * wv.x; hid1 += a * wv.y; hid2 += a * wv.z; hid3 += a * wv.w;
        }
        float4 w2 = ((const float4*)sW2)[lane];
        float p = fmaxf(hid0 + sb1[lane * 4 + 0], 0.f) * w2.x
                + fmaxf(hid1 + sb1[lane * 4 + 1], 0.f) * w2.y
                + fmaxf(hid2 + sb1[lane * 4 + 2], 0.f) * w2.z
                + fmaxf(hid3 + sb1[lane * 4 + 3], 0.f) * w2.w;
#pragma unroll
        for (int o = 16; o > 0; o >>= 1) p += __shfl_down_sync(0xffffffffu, p, o);
        if (lane == 0) out[n] = p + b2v;
        __syncwarp();
    }
}

// ---------------- launch ----------------
extern "C" void kernel_launch(void* const* d_in, const int* in_sizes, int n_in,
                              void* d_out, int out_size) {
    // input order: x, edge_index, edge_type, [n_data], W_in, b_in, W1, b1, W2, b2,
    //              W_ih, b_ih, W_hh, b_hh, Wr1, br1, Wr2, br2
    int base = (n_in >= 18) ? 4 : 3;  // robust to scalar n_data being omitted
    const float* x          = (const float*)d_in[0];
    const int*   edge_index = (const int*)d_in[1];
    const int*   edge_type  = (const int*)d_in[2];
    const float* W_in = (const float*)d_in[base + 0];
    const float* b_in = (const float*)d_in[base + 1];
    const float* W1   = (const float*)d_in[base + 2];
    const float* b1   = (const float*)d_in[base + 3];
    const float* W2   = (const float*)d_in[base + 4];
    const float* b2   = (const float*)d_in[base + 5];
    const float* W_ih = (const float*)d_in[base + 6];
    const float* b_ih = (const float*)d_in[base + 7];
    const float* W_hh = (const float*)d_in[base + 8];
    const float* b_hh = (const float*)d_in[base + 9];
    const float* Wr1  = (const float*)d_in[base + 10];
    const float* br1  = (const float*)d_in[base + 11];
    const float* Wr2  = (const float*)d_in[base + 12];
    const float* br2  = (const float*)d_in[base + 13];
    float* out = (float*)d_out;

    const int EDGE_SMEM = (64 * 256 + 32 * 128) * 4 + 2 * 64 * 4;  // 82944
    const int GRU_SMEM  = (64 * 128 + 32 * 128) * 4;               // 49152
    const int READ_SMEM = (128 * 128 + 128 + 128 + 8 * 128) * 4;   // 70656
    cudaFuncSetAttribute(k_edge_mlp, cudaFuncAttributeMaxDynamicSharedMemorySize, EDGE_SMEM);
    cudaFuncSetAttribute(k_gru_gemm, cudaFuncAttributeMaxDynamicSharedMemorySize, GRU_SMEM);
    cudaFuncSetAttribute(k_readout,  cudaFuncAttributeMaxDynamicSharedMemorySize, READ_SMEM);

    // edge partition by type
    k_zero_cnt<<<1, 32>>>();
    k_count<<<(N_EDGESC + 255) / 256, 256>>>(edge_type);
    k_seed<<<1, 1>>>();
    k_scatter<<<(N_EDGESC + 255) / 256, 256>>>(edge_type);

    // input projection
    k_init<<<(N_NODES * H + 255) / 256, 256>>>(x, W_in, b_in);

    const int NEL = N_NODES * H;
    for (int l = 0; l < 3; ++l) {
        k_zero_agg<<<(NEL + 255) / 256, 256>>>();
        k_edge_mlp<<<N_EDGESC / 64 + 1, 256, EDGE_SMEM>>>(edge_index, W1, b1, W2, b2, l);
        dim3 gg((N_NODES + 63) / 64, 3, 2);
        k_gru_gemm<<<gg, 256, GRU_SMEM>>>(W_ih, b_ih, W_hh, b_hh, l);
        k_gru_combine<<<(NEL + 255) / 256, 256>>>();
    }

    k_readout<<<625, 256, READ_SMEM>>>(Wr1, br1, Wr2, br2, out, out_size);
}